// round 13
// baseline (speedup 1.0000x reference)
#include <cuda_runtime.h>
#include <cuda_fp16.h>
#include <cstdint>

#define D_DIM 512
#define B_DIM 512
#define C_TOT 100000
#define C_PAD 100096            // 782 * 128
#define NTILES_TOT 782
#define SSCALE 64.0f
#define NCHUNK 10

// Scratch (allocation-free rules: __device__ globals)
__device__ __align__(16) __half g_A[B_DIM * D_DIM];            // normalized features, fp16
__device__ __align__(16) __half g_W[(size_t)C_PAD * D_DIM];    // normalized weights, fp16, zero-padded rows

__device__ __forceinline__ uint32_t smem_u32(const void* p) {
    return (uint32_t)__cvta_generic_to_shared(p);
}

// ---------------------------------------------------------------------------
// Kernel 1: normalize features (512 rows), warp per row, write fp16
// ---------------------------------------------------------------------------
__global__ void k_norm_features(const float* __restrict__ f) {
    int row = blockIdx.x * 8 + (threadIdx.x >> 5);
    int lane = threadIdx.x & 31;
    const float4* src = (const float4*)(f + (size_t)row * D_DIM);
    float4 v[4];
    float s = 0.f;
#pragma unroll
    for (int j = 0; j < 4; j++) {
        v[j] = src[lane + 32 * j];
        s += v[j].x * v[j].x + v[j].y * v[j].y + v[j].z * v[j].z + v[j].w * v[j].w;
    }
#pragma unroll
    for (int o = 16; o; o >>= 1) s += __shfl_xor_sync(0xffffffffu, s, o);
    float inv = rsqrtf(s + 1e-12f);
    __half2* d2 = (__half2*)(g_A + (size_t)row * D_DIM);
#pragma unroll
    for (int j = 0; j < 4; j++) {
        int p = (lane + 32 * j) * 2;
        d2[p]     = __floats2half2_rn(v[j].x * inv, v[j].y * inv);
        d2[p + 1] = __floats2half2_rn(v[j].z * inv, v[j].w * inv);
    }
}

// ---------------------------------------------------------------------------
// Kernel 2: normalize a slice of weight rows [row_base, row_base+nrows), fp16
// (rows >= C_TOT get zero fill). One warp per row.
// ---------------------------------------------------------------------------
__global__ void k_norm_weights(const float* __restrict__ w, int row_base, int nrows) {
    int r = blockIdx.x * 8 + (threadIdx.x >> 5);
    int lane = threadIdx.x & 31;
    if (r >= nrows) return;
    int row = row_base + r;
    __half* dst = g_W + (size_t)row * D_DIM;
    if (row >= C_TOT) {
        uint4 z = make_uint4(0u, 0u, 0u, 0u);
#pragma unroll
        for (int j = lane; j < 64; j += 32) ((uint4*)dst)[j] = z;
        return;
    }
    const float4* src = (const float4*)(w + (size_t)row * D_DIM);
    float4 v[4];
    float s = 0.f;
#pragma unroll
    for (int j = 0; j < 4; j++) {
        v[j] = src[lane + 32 * j];
        s += v[j].x * v[j].x + v[j].y * v[j].y + v[j].z * v[j].z + v[j].w * v[j].w;
    }
#pragma unroll
    for (int o = 16; o; o >>= 1) s += __shfl_xor_sync(0xffffffffu, s, o);
    float inv = rsqrtf(s + 1e-12f);
    __half2* d2 = (__half2*)dst;
#pragma unroll
    for (int j = 0; j < 4; j++) {
        int p = (lane + 32 * j) * 2;
        d2[p]     = __floats2half2_rn(v[j].x * inv, v[j].y * inv);
        d2[p + 1] = __floats2half2_rn(v[j].z * inv, v[j].w * inv);
    }
}

// ---------------------------------------------------------------------------
// Kernel 3: GEMM out = 64 * clip(A @ W^T) + fused exact-fp32 margin fixup.
// CTA tile 128x128, 4 warps, warp tile 64x64 (2x2), KC=32, 4-stage cp.async
// ring, coalesced smem-staged epilogue. N-tiles offset by nt_off (chunking).
// ---------------------------------------------------------------------------
#define KC 32
#define NSTG 4
#define KSTAGES (D_DIM / KC)    // 16
#define STAGE_BYTES 20480       // (128 A-rows + 128 B-rows) * 80B
#define GEMM_SMEM (NSTG * STAGE_BYTES)   // 81920 B
#define EPI_LDC 132             // epilogue f32 stride

__global__ __launch_bounds__(128, 2) void k_gemm(
    const float* __restrict__ f, const int* __restrict__ labels,
    const float* __restrict__ w, float* __restrict__ out, int nt_off)
{
    extern __shared__ __align__(16) char smem[];
    __shared__ int s_cnt;
    __shared__ int s_rows[128];
    uint32_t sbase = smem_u32(smem);

    int tid = threadIdx.x;
    int lane = tid & 31;
    int warp = tid >> 5;
    int wm = warp >> 1;              // 0..1
    int wn = warp & 1;               // 0..1
    int bid = blockIdx.x;
    int m0 = (bid & 3) * 128;        // M-tile fastest -> W tile shared via L2
    int n0 = (nt_off + (bid >> 2)) * 128;

    const __half* Ag = g_A + (size_t)m0 * D_DIM;
    const __half* Bg = g_W + (size_t)n0 * D_DIM;

    if (tid == 0) s_cnt = 0;

    float acc[4][8][4];
#pragma unroll
    for (int a = 0; a < 4; a++)
#pragma unroll
        for (int b = 0; b < 8; b++)
#pragma unroll
            for (int c = 0; c < 4; c++) acc[a][b][c] = 0.f;

    // loader: per stage, per matrix 128 rows x 4x16B chunks = 512; 4 passes of 128 thr
    auto load_stage = [&](int ks, int buf) {
        uint32_t sa = sbase + buf * STAGE_BYTES;
        uint32_t sb = sa + 128 * 80;
#pragma unroll
        for (int i = 0; i < 4; i++) {
            int ch = tid + i * 128;      // 0..511
            int r = ch >> 2;             // row 0..127
            int c = ch & 3;              // 16B chunk
            const __half* srcA = Ag + (size_t)r * D_DIM + ks * KC + c * 8;
            const __half* srcB = Bg + (size_t)r * D_DIM + ks * KC + c * 8;
            asm volatile("cp.async.cg.shared.global [%0], [%1], 16;"
                         :: "r"(sa + r * 80 + c * 16), "l"(srcA));
            asm volatile("cp.async.cg.shared.global [%0], [%1], 16;"
                         :: "r"(sb + r * 80 + c * 16), "l"(srcB));
        }
    };

#pragma unroll
    for (int p = 0; p < NSTG - 1; p++) {
        load_stage(p, p);
        asm volatile("cp.async.commit_group;");
    }

    for (int s = 0; s < KSTAGES; s++) {
        asm volatile("cp.async.wait_group %0;" :: "n"(NSTG - 2));
        __syncthreads();

        int nxt = s + NSTG - 1;
        if (nxt < KSTAGES) load_stage(nxt, nxt & (NSTG - 1));
        asm volatile("cp.async.commit_group;");

        uint32_t sa = sbase + (s & (NSTG - 1)) * STAGE_BYTES;
        uint32_t sb = sa + 128 * 80;
#pragma unroll
        for (int kk = 0; kk < 2; kk++) {
            int k0 = kk * 16;
            uint32_t a[4][4], b[8][2];
#pragma unroll
            for (int mi = 0; mi < 4; mi++) {
                int row = wm * 64 + mi * 16 + (lane & 15);
                int col = k0 + ((lane >> 4) << 3);
                uint32_t addr = sa + row * 80 + col * 2;
                asm volatile("ldmatrix.sync.aligned.m8n8.x4.shared.b16 {%0,%1,%2,%3}, [%4];"
                             : "=r"(a[mi][0]), "=r"(a[mi][1]), "=r"(a[mi][2]), "=r"(a[mi][3])
                             : "r"(addr));
            }
#pragma unroll
            for (int p = 0; p < 4; p++) {    // one x4 = 16 n-rows x k16
                int g = lane >> 3;
                int rr = lane & 7;
                int row = wn * 64 + p * 16 + ((g & 2) ? 8 : 0) + rr;
                int col = k0 + ((g & 1) ? 8 : 0);
                uint32_t addr = sb + row * 80 + col * 2;
                asm volatile("ldmatrix.sync.aligned.m8n8.x4.shared.b16 {%0,%1,%2,%3}, [%4];"
                             : "=r"(b[2 * p][0]), "=r"(b[2 * p][1]),
                               "=r"(b[2 * p + 1][0]), "=r"(b[2 * p + 1][1])
                             : "r"(addr));
            }
#pragma unroll
            for (int mi = 0; mi < 4; mi++)
#pragma unroll
                for (int ni = 0; ni < 8; ni++)
                    asm volatile(
                        "mma.sync.aligned.m16n8k16.row.col.f32.f16.f16.f32 "
                        "{%0,%1,%2,%3}, {%4,%5,%6,%7}, {%8,%9}, {%0,%1,%2,%3};"
                        : "+f"(acc[mi][ni][0]), "+f"(acc[mi][ni][1]),
                          "+f"(acc[mi][ni][2]), "+f"(acc[mi][ni][3])
                        : "r"(a[mi][0]), "r"(a[mi][1]), "r"(a[mi][2]), "r"(a[mi][3]),
                          "r"(b[ni][0]), "r"(b[ni][1]));
        }
    }

    // ------- epilogue: stage through smem, fully coalesced float4 stores -----
    __syncthreads();
    float* sT = (float*)smem;              // 128 x EPI_LDC fp32 (67.6 KB <= 80 KB)

#pragma unroll
    for (int mi = 0; mi < 4; mi++) {
        int r0 = wm * 64 + mi * 16 + (lane >> 2);
#pragma unroll
        for (int ni = 0; ni < 8; ni++) {
            int c0 = wn * 64 + ni * 8 + (lane & 3) * 2;
            float2 v0, v1;
            v0.x = SSCALE * fminf(1.f, fmaxf(-1.f, acc[mi][ni][0]));
            v0.y = SSCALE * fminf(1.f, fmaxf(-1.f, acc[mi][ni][1]));
            v1.x = SSCALE * fminf(1.f, fmaxf(-1.f, acc[mi][ni][2]));
            v1.y = SSCALE * fminf(1.f, fmaxf(-1.f, acc[mi][ni][3]));
            *(float2*)&sT[r0 * EPI_LDC + c0] = v0;
            *(float2*)&sT[(r0 + 8) * EPI_LDC + c0] = v1;
        }
    }
    // collect rows whose label column falls inside this N-tile (while waiting)
    {
        int l = labels[m0 + tid];
        if (l >= n0 && l < n0 + 128) {
            int idx = atomicAdd(&s_cnt, 1);
            s_rows[idx] = tid;
        }
    }
    __syncthreads();

    // coalesced stores: 128 threads, warp = row group, lane*4 = col chunk
    int c4 = lane * 4;
    int cg = n0 + c4;
    bool ok = (cg < C_TOT);
#pragma unroll
    for (int it = 0; it < 32; it++) {
        int r = it * 4 + warp;
        if (ok) {
            float4 v = *(float4*)&sT[r * EPI_LDC + c4];
            *(float4*)&out[(size_t)(m0 + r) * C_TOT + cg] = v;
        }
    }
    __syncthreads();   // order plain stores before margin overwrite

    // ------- fused exact-fp32 margin fixup (expected ~0.16 rows per CTA) -----
    int cnt = s_cnt;
    for (int e = warp; e < cnt; e += 4) {
        int r = s_rows[e];
        int lbl = labels[m0 + r];
        const float* fr = f + (size_t)(m0 + r) * D_DIM;
        const float* wr = w + (size_t)lbl * D_DIM;
        float ff = 0.f, ww = 0.f, fw = 0.f;
#pragma unroll
        for (int i = lane; i < D_DIM; i += 32) {
            float av = fr[i], bv = wr[i];
            ff += av * av; ww += bv * bv; fw += av * bv;
        }
#pragma unroll
        for (int o = 16; o; o >>= 1) {
            ff += __shfl_xor_sync(0xffffffffu, ff, o);
            ww += __shfl_xor_sync(0xffffffffu, ww, o);
            fw += __shfl_xor_sync(0xffffffffu, fw, o);
        }
        if (lane == 0) {
            float cosv = fw * rsqrtf(ff + 1e-12f) * rsqrtf(ww + 1e-12f);
            cosv = fminf(1.f, fmaxf(-1.f, cosv));
            const float TH = -0.8775825618903728f;   // cos(pi - 0.5)
            const float MM = 0.2397127693021015f;    // sin(pi - 0.5) * 0.5
            float adj = (cosv > TH) ? cosf(acosf(cosv) + 0.5f) : (cosv - MM);
            out[(size_t)(m0 + r) * C_TOT + lbl] = SSCALE * adj;
        }
    }
}

// ---------------------------------------------------------------------------
// Launch: chunked W-normalization (stream s1) pipelined against GEMM chunks
// alternating on s0 (capture/default) and s2. Graduated chunk sizes shrink
// the startup serialization (gemm chunk 0 waits only for a 16-tile W slice).
// ---------------------------------------------------------------------------
extern "C" void kernel_launch(void* const* d_in, const int* in_sizes, int n_in,
                              void* d_out, int out_size) {
    const float* features = (const float*)d_in[0];   // [512, 512] f32
    const int*   labels   = (const int*)d_in[1];     // [512] i32
    const float* weight   = (const float*)d_in[2];   // [100000, 512] f32
    float* out = (float*)d_out;                      // [512, 100000] f32

    static const int ntc[NCHUNK] = {16, 32, 64, 96, 96, 96, 96, 96, 96, 94}; // sum 782
    static cudaStream_t s1 = nullptr, s2 = nullptr;
    static cudaEvent_t e_root, e_nf, e_w[NCHUNK], e_g2;
    if (s1 == nullptr) {
        cudaStreamCreateWithFlags(&s1, cudaStreamNonBlocking);
        cudaStreamCreateWithFlags(&s2, cudaStreamNonBlocking);
        cudaEventCreateWithFlags(&e_root, cudaEventDisableTiming);
        cudaEventCreateWithFlags(&e_nf, cudaEventDisableTiming);
        cudaEventCreateWithFlags(&e_g2, cudaEventDisableTiming);
        for (int c = 0; c < NCHUNK; c++)
            cudaEventCreateWithFlags(&e_w[c], cudaEventDisableTiming);
        cudaFuncSetAttribute(k_gemm, cudaFuncAttributeMaxDynamicSharedMemorySize, GEMM_SMEM);
    }

    // fork point: s1/s2 join the (possibly capturing) default stream's graph
    cudaEventRecord(e_root, 0);
    cudaStreamWaitEvent(s1, e_root, 0);
    cudaStreamWaitEvent(s2, e_root, 0);

    // features on s0 (fast warp-per-row version)
    k_norm_features<<<B_DIM / 8, 256>>>(features);
    cudaEventRecord(e_nf, 0);
    cudaStreamWaitEvent(s2, e_nf, 0);    // s2 gemms also need nf

    // W-normalization chunks on s1
    int row_base = 0;
    for (int c = 0; c < NCHUNK; c++) {
        int nrows = ntc[c] * 128;
        k_norm_weights<<<nrows / 8, 256, 0, s1>>>(weight, row_base, nrows);
        cudaEventRecord(e_w[c], s1);
        row_base += nrows;
    }

    // GEMM chunks: even on s0, odd on s2
    int nt_off = 0;
    for (int c = 0; c < NCHUNK; c++) {
        cudaStream_t gs = (c & 1) ? s2 : (cudaStream_t)0;
        cudaStreamWaitEvent(gs, e_w[c], 0);
        k_gemm<<<4 * ntc[c], 128, GEMM_SMEM, gs>>>(features, labels, weight, out, nt_off);
        nt_off += ntc[c];
    }

    // join s2 back into s0
    cudaEventRecord(e_g2, s2);
    cudaStreamWaitEvent(0, e_g2, 0);
}

// round 14
// speedup vs baseline: 1.0090x; 1.0090x over previous
#include <cuda_runtime.h>
#include <cuda_fp16.h>
#include <cstdint>

#define D_DIM 512
#define B_DIM 512
#define C_TOT 100000
#define C_PAD 100096            // 782 * 128
#define NTILES_TOT 782
#define SSCALE 64.0f
#define NCHUNK 8

// Scratch (allocation-free rules: __device__ globals)
__device__ __align__(16) __half g_A[B_DIM * D_DIM];            // normalized features, fp16
__device__ __align__(16) __half g_W[(size_t)C_PAD * D_DIM];    // normalized weights, fp16, zero-padded rows

__device__ __forceinline__ uint32_t smem_u32(const void* p) {
    return (uint32_t)__cvta_generic_to_shared(p);
}

// ---------------------------------------------------------------------------
// Kernel 1: normalize features (512 rows), warp per row, write fp16
// ---------------------------------------------------------------------------
__global__ void k_norm_features(const float* __restrict__ f) {
    int row = blockIdx.x * 8 + (threadIdx.x >> 5);
    int lane = threadIdx.x & 31;
    const float4* src = (const float4*)(f + (size_t)row * D_DIM);
    float4 v[4];
    float s = 0.f;
#pragma unroll
    for (int j = 0; j < 4; j++) {
        v[j] = src[lane + 32 * j];
        s += v[j].x * v[j].x + v[j].y * v[j].y + v[j].z * v[j].z + v[j].w * v[j].w;
    }
#pragma unroll
    for (int o = 16; o; o >>= 1) s += __shfl_xor_sync(0xffffffffu, s, o);
    float inv = rsqrtf(s + 1e-12f);
    __half2* d2 = (__half2*)(g_A + (size_t)row * D_DIM);
#pragma unroll
    for (int j = 0; j < 4; j++) {
        int p = (lane + 32 * j) * 2;
        d2[p]     = __floats2half2_rn(v[j].x * inv, v[j].y * inv);
        d2[p + 1] = __floats2half2_rn(v[j].z * inv, v[j].w * inv);
    }
}

// ---------------------------------------------------------------------------
// Kernel 2: normalize a slice of weight rows [row_base, row_base+nrows), fp16
// (rows >= C_TOT get zero fill). One warp per row.
// ---------------------------------------------------------------------------
__global__ void k_norm_weights(const float* __restrict__ w, int row_base, int nrows) {
    int r = blockIdx.x * 8 + (threadIdx.x >> 5);
    int lane = threadIdx.x & 31;
    if (r >= nrows) return;
    int row = row_base + r;
    __half* dst = g_W + (size_t)row * D_DIM;
    if (row >= C_TOT) {
        uint4 z = make_uint4(0u, 0u, 0u, 0u);
#pragma unroll
        for (int j = lane; j < 64; j += 32) ((uint4*)dst)[j] = z;
        return;
    }
    const float4* src = (const float4*)(w + (size_t)row * D_DIM);
    float4 v[4];
    float s = 0.f;
#pragma unroll
    for (int j = 0; j < 4; j++) {
        v[j] = src[lane + 32 * j];
        s += v[j].x * v[j].x + v[j].y * v[j].y + v[j].z * v[j].z + v[j].w * v[j].w;
    }
#pragma unroll
    for (int o = 16; o; o >>= 1) s += __shfl_xor_sync(0xffffffffu, s, o);
    float inv = rsqrtf(s + 1e-12f);
    __half2* d2 = (__half2*)dst;
#pragma unroll
    for (int j = 0; j < 4; j++) {
        int p = (lane + 32 * j) * 2;
        d2[p]     = __floats2half2_rn(v[j].x * inv, v[j].y * inv);
        d2[p + 1] = __floats2half2_rn(v[j].z * inv, v[j].w * inv);
    }
}

// ---------------------------------------------------------------------------
// Kernel 3: GEMM out = 64 * clip(A @ W^T) + fused exact-fp32 margin fixup.
// CTA tile 128x128, 4 warps, warp tile 64x64 (2x2), KC=32, 4-stage cp.async
// ring, coalesced smem-staged epilogue. N-tiles offset by nt_off (chunking).
// ---------------------------------------------------------------------------
#define KC 32
#define NSTG 4
#define KSTAGES (D_DIM / KC)    // 16
#define STAGE_BYTES 20480       // (128 A-rows + 128 B-rows) * 80B
#define GEMM_SMEM (NSTG * STAGE_BYTES)   // 81920 B
#define EPI_LDC 132             // epilogue f32 stride

__global__ __launch_bounds__(128, 2) void k_gemm(
    const float* __restrict__ f, const int* __restrict__ labels,
    const float* __restrict__ w, float* __restrict__ out, int nt_off)
{
    extern __shared__ __align__(16) char smem[];
    __shared__ int s_cnt;
    __shared__ int s_rows[128];
    uint32_t sbase = smem_u32(smem);

    int tid = threadIdx.x;
    int lane = tid & 31;
    int warp = tid >> 5;
    int wm = warp >> 1;              // 0..1
    int wn = warp & 1;               // 0..1
    int bid = blockIdx.x;
    int m0 = (bid & 3) * 128;        // M-tile fastest -> W tile shared via L2
    int n0 = (nt_off + (bid >> 2)) * 128;

    const __half* Ag = g_A + (size_t)m0 * D_DIM;
    const __half* Bg = g_W + (size_t)n0 * D_DIM;

    if (tid == 0) s_cnt = 0;

    float acc[4][8][4];
#pragma unroll
    for (int a = 0; a < 4; a++)
#pragma unroll
        for (int b = 0; b < 8; b++)
#pragma unroll
            for (int c = 0; c < 4; c++) acc[a][b][c] = 0.f;

    // loader: per stage, per matrix 128 rows x 4x16B chunks = 512; 4 passes of 128 thr
    auto load_stage = [&](int ks, int buf) {
        uint32_t sa = sbase + buf * STAGE_BYTES;
        uint32_t sb = sa + 128 * 80;
#pragma unroll
        for (int i = 0; i < 4; i++) {
            int ch = tid + i * 128;      // 0..511
            int r = ch >> 2;             // row 0..127
            int c = ch & 3;              // 16B chunk
            const __half* srcA = Ag + (size_t)r * D_DIM + ks * KC + c * 8;
            const __half* srcB = Bg + (size_t)r * D_DIM + ks * KC + c * 8;
            asm volatile("cp.async.cg.shared.global [%0], [%1], 16;"
                         :: "r"(sa + r * 80 + c * 16), "l"(srcA));
            asm volatile("cp.async.cg.shared.global [%0], [%1], 16;"
                         :: "r"(sb + r * 80 + c * 16), "l"(srcB));
        }
    };

#pragma unroll
    for (int p = 0; p < NSTG - 1; p++) {
        load_stage(p, p);
        asm volatile("cp.async.commit_group;");
    }

    for (int s = 0; s < KSTAGES; s++) {
        asm volatile("cp.async.wait_group %0;" :: "n"(NSTG - 2));
        __syncthreads();

        int nxt = s + NSTG - 1;
        if (nxt < KSTAGES) load_stage(nxt, nxt & (NSTG - 1));
        asm volatile("cp.async.commit_group;");

        uint32_t sa = sbase + (s & (NSTG - 1)) * STAGE_BYTES;
        uint32_t sb = sa + 128 * 80;
#pragma unroll
        for (int kk = 0; kk < 2; kk++) {
            int k0 = kk * 16;
            uint32_t a[4][4], b[8][2];
#pragma unroll
            for (int mi = 0; mi < 4; mi++) {
                int row = wm * 64 + mi * 16 + (lane & 15);
                int col = k0 + ((lane >> 4) << 3);
                uint32_t addr = sa + row * 80 + col * 2;
                asm volatile("ldmatrix.sync.aligned.m8n8.x4.shared.b16 {%0,%1,%2,%3}, [%4];"
                             : "=r"(a[mi][0]), "=r"(a[mi][1]), "=r"(a[mi][2]), "=r"(a[mi][3])
                             : "r"(addr));
            }
#pragma unroll
            for (int p = 0; p < 4; p++) {    // one x4 = 16 n-rows x k16
                int g = lane >> 3;
                int rr = lane & 7;
                int row = wn * 64 + p * 16 + ((g & 2) ? 8 : 0) + rr;
                int col = k0 + ((g & 1) ? 8 : 0);
                uint32_t addr = sb + row * 80 + col * 2;
                asm volatile("ldmatrix.sync.aligned.m8n8.x4.shared.b16 {%0,%1,%2,%3}, [%4];"
                             : "=r"(b[2 * p][0]), "=r"(b[2 * p][1]),
                               "=r"(b[2 * p + 1][0]), "=r"(b[2 * p + 1][1])
                             : "r"(addr));
            }
#pragma unroll
            for (int mi = 0; mi < 4; mi++)
#pragma unroll
                for (int ni = 0; ni < 8; ni++)
                    asm volatile(
                        "mma.sync.aligned.m16n8k16.row.col.f32.f16.f16.f32 "
                        "{%0,%1,%2,%3}, {%4,%5,%6,%7}, {%8,%9}, {%0,%1,%2,%3};"
                        : "+f"(acc[mi][ni][0]), "+f"(acc[mi][ni][1]),
                          "+f"(acc[mi][ni][2]), "+f"(acc[mi][ni][3])
                        : "r"(a[mi][0]), "r"(a[mi][1]), "r"(a[mi][2]), "r"(a[mi][3]),
                          "r"(b[ni][0]), "r"(b[ni][1]));
        }
    }

    // ------- epilogue: stage through smem, fully coalesced float4 stores -----
    __syncthreads();
    float* sT = (float*)smem;              // 128 x EPI_LDC fp32 (67.6 KB <= 80 KB)

#pragma unroll
    for (int mi = 0; mi < 4; mi++) {
        int r0 = wm * 64 + mi * 16 + (lane >> 2);
#pragma unroll
        for (int ni = 0; ni < 8; ni++) {
            int c0 = wn * 64 + ni * 8 + (lane & 3) * 2;
            float2 v0, v1;
            v0.x = SSCALE * fminf(1.f, fmaxf(-1.f, acc[mi][ni][0]));
            v0.y = SSCALE * fminf(1.f, fmaxf(-1.f, acc[mi][ni][1]));
            v1.x = SSCALE * fminf(1.f, fmaxf(-1.f, acc[mi][ni][2]));
            v1.y = SSCALE * fminf(1.f, fmaxf(-1.f, acc[mi][ni][3]));
            *(float2*)&sT[r0 * EPI_LDC + c0] = v0;
            *(float2*)&sT[(r0 + 8) * EPI_LDC + c0] = v1;
        }
    }
    // collect rows whose label column falls inside this N-tile (while waiting)
    {
        int l = labels[m0 + tid];
        if (l >= n0 && l < n0 + 128) {
            int idx = atomicAdd(&s_cnt, 1);
            s_rows[idx] = tid;
        }
    }
    __syncthreads();

    // coalesced stores: 128 threads, warp = row group, lane*4 = col chunk
    int c4 = lane * 4;
    int cg = n0 + c4;
    bool ok = (cg < C_TOT);
#pragma unroll
    for (int it = 0; it < 32; it++) {
        int r = it * 4 + warp;
        if (ok) {
            float4 v = *(float4*)&sT[r * EPI_LDC + c4];
            *(float4*)&out[(size_t)(m0 + r) * C_TOT + cg] = v;
        }
    }
    __syncthreads();   // order plain stores before margin overwrite

    // ------- fused exact-fp32 margin fixup (expected ~0.16 rows per CTA) -----
    int cnt = s_cnt;
    for (int e = warp; e < cnt; e += 4) {
        int r = s_rows[e];
        int lbl = labels[m0 + r];
        const float* fr = f + (size_t)(m0 + r) * D_DIM;
        const float* wr = w + (size_t)lbl * D_DIM;
        float ff = 0.f, ww = 0.f, fw = 0.f;
#pragma unroll
        for (int i = lane; i < D_DIM; i += 32) {
            float av = fr[i], bv = wr[i];
            ff += av * av; ww += bv * bv; fw += av * bv;
        }
#pragma unroll
        for (int o = 16; o; o >>= 1) {
            ff += __shfl_xor_sync(0xffffffffu, ff, o);
            ww += __shfl_xor_sync(0xffffffffu, ww, o);
            fw += __shfl_xor_sync(0xffffffffu, fw, o);
        }
        if (lane == 0) {
            float cosv = fw * rsqrtf(ff + 1e-12f) * rsqrtf(ww + 1e-12f);
            cosv = fminf(1.f, fmaxf(-1.f, cosv));
            const float TH = -0.8775825618903728f;   // cos(pi - 0.5)
            const float MM = 0.2397127693021015f;    // sin(pi - 0.5) * 0.5
            float adj = (cosv > TH) ? cosf(acosf(cosv) + 0.5f) : (cosv - MM);
            out[(size_t)(m0 + r) * C_TOT + lbl] = SSCALE * adj;
        }
    }
}

// ---------------------------------------------------------------------------
// Launch: chunked W-normalization (stream s1) pipelined against GEMM chunks
// alternating on s0 (capture/default) and s2. Same 8-chunk structure that
// measured best (R12), with only chunk 0 shrunk to cut startup serialization.
// ---------------------------------------------------------------------------
extern "C" void kernel_launch(void* const* d_in, const int* in_sizes, int n_in,
                              void* d_out, int out_size) {
    const float* features = (const float*)d_in[0];   // [512, 512] f32
    const int*   labels   = (const int*)d_in[1];     // [512] i32
    const float* weight   = (const float*)d_in[2];   // [100000, 512] f32
    float* out = (float*)d_out;                      // [512, 100000] f32

    static const int ntc[NCHUNK] = {32, 98, 98, 98, 98, 98, 98, 162}; // sum 782
    static cudaStream_t s1 = nullptr, s2 = nullptr;
    static cudaEvent_t e_root, e_nf, e_w[NCHUNK], e_g2;
    if (s1 == nullptr) {
        cudaStreamCreateWithFlags(&s1, cudaStreamNonBlocking);
        cudaStreamCreateWithFlags(&s2, cudaStreamNonBlocking);
        cudaEventCreateWithFlags(&e_root, cudaEventDisableTiming);
        cudaEventCreateWithFlags(&e_nf, cudaEventDisableTiming);
        cudaEventCreateWithFlags(&e_g2, cudaEventDisableTiming);
        for (int c = 0; c < NCHUNK; c++)
            cudaEventCreateWithFlags(&e_w[c], cudaEventDisableTiming);
        cudaFuncSetAttribute(k_gemm, cudaFuncAttributeMaxDynamicSharedMemorySize, GEMM_SMEM);
    }

    // fork point: s1/s2 join the (possibly capturing) default stream's graph
    cudaEventRecord(e_root, 0);
    cudaStreamWaitEvent(s1, e_root, 0);
    cudaStreamWaitEvent(s2, e_root, 0);

    // features on s0 (fast warp-per-row version)
    k_norm_features<<<B_DIM / 8, 256>>>(features);
    cudaEventRecord(e_nf, 0);
    cudaStreamWaitEvent(s2, e_nf, 0);    // s2 gemms also need nf

    // W-normalization chunks on s1
    int row_base = 0;
    for (int c = 0; c < NCHUNK; c++) {
        int nrows = ntc[c] * 128;
        k_norm_weights<<<nrows / 8, 256, 0, s1>>>(weight, row_base, nrows);
        cudaEventRecord(e_w[c], s1);
        row_base += nrows;
    }

    // GEMM chunks: even on s0, odd on s2
    int nt_off = 0;
    for (int c = 0; c < NCHUNK; c++) {
        cudaStream_t gs = (c & 1) ? s2 : (cudaStream_t)0;
        cudaStreamWaitEvent(gs, e_w[c], 0);
        k_gemm<<<4 * ntc[c], 128, GEMM_SMEM, gs>>>(features, labels, weight, out, nt_off);
        nt_off += ntc[c];
    }

    // join s2 back into s0
    cudaEventRecord(e_g2, s2);
    cudaStreamWaitEvent(0, e_g2, 0);
}

// round 15
// speedup vs baseline: 1.0162x; 1.0071x over previous
#include <cuda_runtime.h>
#include <cuda_fp16.h>
#include <cstdint>

#define D_DIM 512
#define B_DIM 512
#define C_TOT 100000
#define C_PAD 100096            // 782 * 128
#define NTILES_TOT 782
#define SSCALE 64.0f
#define NCHUNK 8

// Scratch (allocation-free rules: __device__ globals)
__device__ __align__(16) __half g_A[B_DIM * D_DIM];            // normalized features, fp16
__device__ __align__(16) __half g_W[(size_t)C_PAD * D_DIM];    // normalized weights, fp16, zero-padded rows

__device__ __forceinline__ uint32_t smem_u32(const void* p) {
    return (uint32_t)__cvta_generic_to_shared(p);
}

// ---------------------------------------------------------------------------
// Kernel 1: normalize features (512 rows), warp per row, write fp16
// ---------------------------------------------------------------------------
__global__ void k_norm_features(const float* __restrict__ f) {
    int row = blockIdx.x * 8 + (threadIdx.x >> 5);
    int lane = threadIdx.x & 31;
    const float4* src = (const float4*)(f + (size_t)row * D_DIM);
    float4 v[4];
    float s = 0.f;
#pragma unroll
    for (int j = 0; j < 4; j++) {
        v[j] = src[lane + 32 * j];
        s += v[j].x * v[j].x + v[j].y * v[j].y + v[j].z * v[j].z + v[j].w * v[j].w;
    }
#pragma unroll
    for (int o = 16; o; o >>= 1) s += __shfl_xor_sync(0xffffffffu, s, o);
    float inv = rsqrtf(s + 1e-12f);
    __half2* d2 = (__half2*)(g_A + (size_t)row * D_DIM);
#pragma unroll
    for (int j = 0; j < 4; j++) {
        int p = (lane + 32 * j) * 2;
        d2[p]     = __floats2half2_rn(v[j].x * inv, v[j].y * inv);
        d2[p + 1] = __floats2half2_rn(v[j].z * inv, v[j].w * inv);
    }
}

// ---------------------------------------------------------------------------
// Kernel 2: normalize a slice of weight rows [row_base, row_base+nrows), fp16
// (rows >= C_TOT get zero fill). One warp per row.
// ---------------------------------------------------------------------------
__global__ void k_norm_weights(const float* __restrict__ w, int row_base, int nrows) {
    int r = blockIdx.x * 8 + (threadIdx.x >> 5);
    int lane = threadIdx.x & 31;
    if (r >= nrows) return;
    int row = row_base + r;
    __half* dst = g_W + (size_t)row * D_DIM;
    if (row >= C_TOT) {
        uint4 z = make_uint4(0u, 0u, 0u, 0u);
#pragma unroll
        for (int j = lane; j < 64; j += 32) ((uint4*)dst)[j] = z;
        return;
    }
    const float4* src = (const float4*)(w + (size_t)row * D_DIM);
    float4 v[4];
    float s = 0.f;
#pragma unroll
    for (int j = 0; j < 4; j++) {
        v[j] = src[lane + 32 * j];
        s += v[j].x * v[j].x + v[j].y * v[j].y + v[j].z * v[j].z + v[j].w * v[j].w;
    }
#pragma unroll
    for (int o = 16; o; o >>= 1) s += __shfl_xor_sync(0xffffffffu, s, o);
    float inv = rsqrtf(s + 1e-12f);
    __half2* d2 = (__half2*)dst;
#pragma unroll
    for (int j = 0; j < 4; j++) {
        int p = (lane + 32 * j) * 2;
        d2[p]     = __floats2half2_rn(v[j].x * inv, v[j].y * inv);
        d2[p + 1] = __floats2half2_rn(v[j].z * inv, v[j].w * inv);
    }
}

// ---------------------------------------------------------------------------
// Kernel 3: GEMM out = 64 * clip(A @ W^T) + fused exact-fp32 margin fixup.
// CTA tile 128x128, 4 warps, warp tile 64x64 (2x2), KC=32, 4-stage cp.async
// ring, coalesced smem-staged epilogue. N-tiles offset by nt_off (chunking).
// ---------------------------------------------------------------------------
#define KC 32
#define NSTG 4
#define KSTAGES (D_DIM / KC)    // 16
#define STAGE_BYTES 20480       // (128 A-rows + 128 B-rows) * 80B
#define GEMM_SMEM (NSTG * STAGE_BYTES)   // 81920 B
#define EPI_LDC 132             // epilogue f32 stride

__global__ __launch_bounds__(128, 2) void k_gemm(
    const float* __restrict__ f, const int* __restrict__ labels,
    const float* __restrict__ w, float* __restrict__ out, int nt_off)
{
    extern __shared__ __align__(16) char smem[];
    __shared__ int s_cnt;
    __shared__ int s_rows[128];
    uint32_t sbase = smem_u32(smem);

    int tid = threadIdx.x;
    int lane = tid & 31;
    int warp = tid >> 5;
    int wm = warp >> 1;              // 0..1
    int wn = warp & 1;               // 0..1
    int bid = blockIdx.x;
    int m0 = (bid & 3) * 128;        // M-tile fastest -> W tile shared via L2
    int n0 = (nt_off + (bid >> 2)) * 128;

    const __half* Ag = g_A + (size_t)m0 * D_DIM;
    const __half* Bg = g_W + (size_t)n0 * D_DIM;

    if (tid == 0) s_cnt = 0;

    float acc[4][8][4];
#pragma unroll
    for (int a = 0; a < 4; a++)
#pragma unroll
        for (int b = 0; b < 8; b++)
#pragma unroll
            for (int c = 0; c < 4; c++) acc[a][b][c] = 0.f;

    // loader: per stage, per matrix 128 rows x 4x16B chunks = 512; 4 passes of 128 thr
    auto load_stage = [&](int ks, int buf) {
        uint32_t sa = sbase + buf * STAGE_BYTES;
        uint32_t sb = sa + 128 * 80;
#pragma unroll
        for (int i = 0; i < 4; i++) {
            int ch = tid + i * 128;      // 0..511
            int r = ch >> 2;             // row 0..127
            int c = ch & 3;              // 16B chunk
            const __half* srcA = Ag + (size_t)r * D_DIM + ks * KC + c * 8;
            const __half* srcB = Bg + (size_t)r * D_DIM + ks * KC + c * 8;
            asm volatile("cp.async.cg.shared.global [%0], [%1], 16;"
                         :: "r"(sa + r * 80 + c * 16), "l"(srcA));
            asm volatile("cp.async.cg.shared.global [%0], [%1], 16;"
                         :: "r"(sb + r * 80 + c * 16), "l"(srcB));
        }
    };

#pragma unroll
    for (int p = 0; p < NSTG - 1; p++) {
        load_stage(p, p);
        asm volatile("cp.async.commit_group;");
    }

    for (int s = 0; s < KSTAGES; s++) {
        asm volatile("cp.async.wait_group %0;" :: "n"(NSTG - 2));
        __syncthreads();

        int nxt = s + NSTG - 1;
        if (nxt < KSTAGES) load_stage(nxt, nxt & (NSTG - 1));
        asm volatile("cp.async.commit_group;");

        uint32_t sa = sbase + (s & (NSTG - 1)) * STAGE_BYTES;
        uint32_t sb = sa + 128 * 80;
#pragma unroll
        for (int kk = 0; kk < 2; kk++) {
            int k0 = kk * 16;
            uint32_t a[4][4], b[8][2];
#pragma unroll
            for (int mi = 0; mi < 4; mi++) {
                int row = wm * 64 + mi * 16 + (lane & 15);
                int col = k0 + ((lane >> 4) << 3);
                uint32_t addr = sa + row * 80 + col * 2;
                asm volatile("ldmatrix.sync.aligned.m8n8.x4.shared.b16 {%0,%1,%2,%3}, [%4];"
                             : "=r"(a[mi][0]), "=r"(a[mi][1]), "=r"(a[mi][2]), "=r"(a[mi][3])
                             : "r"(addr));
            }
#pragma unroll
            for (int p = 0; p < 4; p++) {    // one x4 = 16 n-rows x k16
                int g = lane >> 3;
                int rr = lane & 7;
                int row = wn * 64 + p * 16 + ((g & 2) ? 8 : 0) + rr;
                int col = k0 + ((g & 1) ? 8 : 0);
                uint32_t addr = sb + row * 80 + col * 2;
                asm volatile("ldmatrix.sync.aligned.m8n8.x4.shared.b16 {%0,%1,%2,%3}, [%4];"
                             : "=r"(b[2 * p][0]), "=r"(b[2 * p][1]),
                               "=r"(b[2 * p + 1][0]), "=r"(b[2 * p + 1][1])
                             : "r"(addr));
            }
#pragma unroll
            for (int mi = 0; mi < 4; mi++)
#pragma unroll
                for (int ni = 0; ni < 8; ni++)
                    asm volatile(
                        "mma.sync.aligned.m16n8k16.row.col.f32.f16.f16.f32 "
                        "{%0,%1,%2,%3}, {%4,%5,%6,%7}, {%8,%9}, {%0,%1,%2,%3};"
                        : "+f"(acc[mi][ni][0]), "+f"(acc[mi][ni][1]),
                          "+f"(acc[mi][ni][2]), "+f"(acc[mi][ni][3])
                        : "r"(a[mi][0]), "r"(a[mi][1]), "r"(a[mi][2]), "r"(a[mi][3]),
                          "r"(b[ni][0]), "r"(b[ni][1]));
        }
    }

    // ------- epilogue: stage through smem, fully coalesced float4 stores -----
    __syncthreads();
    float* sT = (float*)smem;              // 128 x EPI_LDC fp32 (67.6 KB <= 80 KB)

#pragma unroll
    for (int mi = 0; mi < 4; mi++) {
        int r0 = wm * 64 + mi * 16 + (lane >> 2);
#pragma unroll
        for (int ni = 0; ni < 8; ni++) {
            int c0 = wn * 64 + ni * 8 + (lane & 3) * 2;
            float2 v0, v1;
            v0.x = SSCALE * fminf(1.f, fmaxf(-1.f, acc[mi][ni][0]));
            v0.y = SSCALE * fminf(1.f, fmaxf(-1.f, acc[mi][ni][1]));
            v1.x = SSCALE * fminf(1.f, fmaxf(-1.f, acc[mi][ni][2]));
            v1.y = SSCALE * fminf(1.f, fmaxf(-1.f, acc[mi][ni][3]));
            *(float2*)&sT[r0 * EPI_LDC + c0] = v0;
            *(float2*)&sT[(r0 + 8) * EPI_LDC + c0] = v1;
        }
    }
    // collect rows whose label column falls inside this N-tile (while waiting)
    {
        int l = labels[m0 + tid];
        if (l >= n0 && l < n0 + 128) {
            int idx = atomicAdd(&s_cnt, 1);
            s_rows[idx] = tid;
        }
    }
    __syncthreads();

    // coalesced stores: 128 threads, warp = row group, lane*4 = col chunk
    int c4 = lane * 4;
    int cg = n0 + c4;
    bool ok = (cg < C_TOT);
#pragma unroll
    for (int it = 0; it < 32; it++) {
        int r = it * 4 + warp;
        if (ok) {
            float4 v = *(float4*)&sT[r * EPI_LDC + c4];
            *(float4*)&out[(size_t)(m0 + r) * C_TOT + cg] = v;
        }
    }
    __syncthreads();   // order plain stores before margin overwrite

    // ------- fused exact-fp32 margin fixup (expected ~0.16 rows per CTA) -----
    int cnt = s_cnt;
    for (int e = warp; e < cnt; e += 4) {
        int r = s_rows[e];
        int lbl = labels[m0 + r];
        const float* fr = f + (size_t)(m0 + r) * D_DIM;
        const float* wr = w + (size_t)lbl * D_DIM;
        float ff = 0.f, ww = 0.f, fw = 0.f;
#pragma unroll
        for (int i = lane; i < D_DIM; i += 32) {
            float av = fr[i], bv = wr[i];
            ff += av * av; ww += bv * bv; fw += av * bv;
        }
#pragma unroll
        for (int o = 16; o; o >>= 1) {
            ff += __shfl_xor_sync(0xffffffffu, ff, o);
            ww += __shfl_xor_sync(0xffffffffu, ww, o);
            fw += __shfl_xor_sync(0xffffffffu, fw, o);
        }
        if (lane == 0) {
            float cosv = fw * rsqrtf(ff + 1e-12f) * rsqrtf(ww + 1e-12f);
            cosv = fminf(1.f, fmaxf(-1.f, cosv));
            const float TH = -0.8775825618903728f;   // cos(pi - 0.5)
            const float MM = 0.2397127693021015f;    // sin(pi - 0.5) * 0.5
            float adj = (cosv > TH) ? cosf(acosf(cosv) + 0.5f) : (cosv - MM);
            out[(size_t)(m0 + r) * C_TOT + lbl] = SSCALE * adj;
        }
    }
}

// ---------------------------------------------------------------------------
// Launch: exact R12 schedule (best measured: uniform 98-tile chunks) with the
// faster warp-per-row feature normalization. No other changes.
// ---------------------------------------------------------------------------
extern "C" void kernel_launch(void* const* d_in, const int* in_sizes, int n_in,
                              void* d_out, int out_size) {
    const float* features = (const float*)d_in[0];   // [512, 512] f32
    const int*   labels   = (const int*)d_in[1];     // [512] i32
    const float* weight   = (const float*)d_in[2];   // [100000, 512] f32
    float* out = (float*)d_out;                      // [512, 100000] f32

    static const int ntc[NCHUNK] = {98, 98, 98, 98, 98, 98, 97, 97}; // sum 782
    static cudaStream_t s1 = nullptr, s2 = nullptr;
    static cudaEvent_t e_root, e_nf, e_w[NCHUNK], e_g2;
    if (s1 == nullptr) {
        cudaStreamCreateWithFlags(&s1, cudaStreamNonBlocking);
        cudaStreamCreateWithFlags(&s2, cudaStreamNonBlocking);
        cudaEventCreateWithFlags(&e_root, cudaEventDisableTiming);
        cudaEventCreateWithFlags(&e_nf, cudaEventDisableTiming);
        cudaEventCreateWithFlags(&e_g2, cudaEventDisableTiming);
        for (int c = 0; c < NCHUNK; c++)
            cudaEventCreateWithFlags(&e_w[c], cudaEventDisableTiming);
        cudaFuncSetAttribute(k_gemm, cudaFuncAttributeMaxDynamicSharedMemorySize, GEMM_SMEM);
    }

    // fork point: s1/s2 join the (possibly capturing) default stream's graph
    cudaEventRecord(e_root, 0);
    cudaStreamWaitEvent(s1, e_root, 0);
    cudaStreamWaitEvent(s2, e_root, 0);

    // features on s0 (fast warp-per-row version)
    k_norm_features<<<B_DIM / 8, 256>>>(features);
    cudaEventRecord(e_nf, 0);
    cudaStreamWaitEvent(s2, e_nf, 0);    // s2 gemms also need nf

    // W-normalization chunks on s1
    int row_base = 0;
    for (int c = 0; c < NCHUNK; c++) {
        int nrows = ntc[c] * 128;
        k_norm_weights<<<nrows / 8, 256, 0, s1>>>(weight, row_base, nrows);
        cudaEventRecord(e_w[c], s1);
        row_base += nrows;
    }

    // GEMM chunks: even on s0, odd on s2
    int nt_off = 0;
    for (int c = 0; c < NCHUNK; c++) {
        cudaStream_t gs = (c & 1) ? s2 : (cudaStream_t)0;
        cudaStreamWaitEvent(gs, e_w[c], 0);
        k_gemm<<<4 * ntc[c], 128, GEMM_SMEM, gs>>>(features, labels, weight, out, nt_off);
        nt_off += ntc[c];
    }

    // join s2 back into s0
    cudaEventRecord(e_g2, s2);
    cudaStreamWaitEvent(0, e_g2, 0);
}

// round 16
// speedup vs baseline: 1.0572x; 1.0404x over previous
#include <cuda_runtime.h>
#include <cuda_fp16.h>
#include <cstdint>

#define D_DIM 512
#define B_DIM 512
#define C_TOT 100000
#define C_PAD 100096            // 782 * 128
#define NTILES_TOT 782
#define SSCALE 64.0f
#define NCHUNK 8

// Scratch (allocation-free rules: __device__ globals)
__device__ __align__(16) __half g_A[B_DIM * D_DIM];            // normalized features, fp16
__device__ __align__(16) __half g_W[(size_t)C_PAD * D_DIM];    // normalized weights, fp16, zero-padded rows

__device__ __forceinline__ uint32_t smem_u32(const void* p) {
    return (uint32_t)__cvta_generic_to_shared(p);
}

// ---------------------------------------------------------------------------
// Kernel 1: normalize features (512 rows), warp per row, write fp16
// ---------------------------------------------------------------------------
__global__ void k_norm_features(const float* __restrict__ f) {
    int row = blockIdx.x * 8 + (threadIdx.x >> 5);
    int lane = threadIdx.x & 31;
    const float4* src = (const float4*)(f + (size_t)row * D_DIM);
    float4 v[4];
    float s = 0.f;
#pragma unroll
    for (int j = 0; j < 4; j++) {
        v[j] = src[lane + 32 * j];
        s += v[j].x * v[j].x + v[j].y * v[j].y + v[j].z * v[j].z + v[j].w * v[j].w;
    }
#pragma unroll
    for (int o = 16; o; o >>= 1) s += __shfl_xor_sync(0xffffffffu, s, o);
    float inv = rsqrtf(s + 1e-12f);
    __half2* d2 = (__half2*)(g_A + (size_t)row * D_DIM);
#pragma unroll
    for (int j = 0; j < 4; j++) {
        int p = (lane + 32 * j) * 2;
        d2[p]     = __floats2half2_rn(v[j].x * inv, v[j].y * inv);
        d2[p + 1] = __floats2half2_rn(v[j].z * inv, v[j].w * inv);
    }
}

// ---------------------------------------------------------------------------
// Kernel 2: normalize a slice of weight rows [row_base, row_base+nrows), fp16
// (rows >= C_TOT get zero fill). One warp per row.
// ---------------------------------------------------------------------------
__global__ void k_norm_weights(const float* __restrict__ w, int row_base, int nrows) {
    int r = blockIdx.x * 8 + (threadIdx.x >> 5);
    int lane = threadIdx.x & 31;
    if (r >= nrows) return;
    int row = row_base + r;
    __half* dst = g_W + (size_t)row * D_DIM;
    if (row >= C_TOT) {
        uint4 z = make_uint4(0u, 0u, 0u, 0u);
#pragma unroll
        for (int j = lane; j < 64; j += 32) ((uint4*)dst)[j] = z;
        return;
    }
    const float4* src = (const float4*)(w + (size_t)row * D_DIM);
    float4 v[4];
    float s = 0.f;
#pragma unroll
    for (int j = 0; j < 4; j++) {
        v[j] = src[lane + 32 * j];
        s += v[j].x * v[j].x + v[j].y * v[j].y + v[j].z * v[j].z + v[j].w * v[j].w;
    }
#pragma unroll
    for (int o = 16; o; o >>= 1) s += __shfl_xor_sync(0xffffffffu, s, o);
    float inv = rsqrtf(s + 1e-12f);
    __half2* d2 = (__half2*)dst;
#pragma unroll
    for (int j = 0; j < 4; j++) {
        int p = (lane + 32 * j) * 2;
        d2[p]     = __floats2half2_rn(v[j].x * inv, v[j].y * inv);
        d2[p + 1] = __floats2half2_rn(v[j].z * inv, v[j].w * inv);
    }
}

// ---------------------------------------------------------------------------
// Kernel 3: GEMM out = 64 * clip(A @ W^T) + fused exact-fp32 margin fixup.
// CTA tile 128x128, 4 warps, warp tile 64x64 (2x2), KC=32, 3-stage cp.async
// ring -> 3 CTAs/SM (3 warps/SMSP keeps the tensor pipe fed across barriers
// and epilogues). Epilogue in two 64-row halves to fit the smaller smem.
// ---------------------------------------------------------------------------
#define KC 32
#define NSTG 3
#define KSTAGES (D_DIM / KC)    // 16
#define STAGE_BYTES 20480       // (128 A-rows + 128 B-rows) * 80B
#define GEMM_SMEM (NSTG * STAGE_BYTES)   // 61440 B -> 3 CTAs/SM
#define EPI_LDC 132             // epilogue f32 stride

__global__ __launch_bounds__(128, 3) void k_gemm(
    const float* __restrict__ f, const int* __restrict__ labels,
    const float* __restrict__ w, float* __restrict__ out, int nt_off)
{
    extern __shared__ __align__(16) char smem[];
    __shared__ int s_cnt;
    __shared__ int s_rows[128];
    uint32_t sbase = smem_u32(smem);

    int tid = threadIdx.x;
    int lane = tid & 31;
    int warp = tid >> 5;
    int wm = warp >> 1;              // 0..1
    int wn = warp & 1;               // 0..1
    int bid = blockIdx.x;
    int m0 = (bid & 3) * 128;        // M-tile fastest -> W tile shared via L2
    int n0 = (nt_off + (bid >> 2)) * 128;

    const __half* Ag = g_A + (size_t)m0 * D_DIM;
    const __half* Bg = g_W + (size_t)n0 * D_DIM;

    if (tid == 0) s_cnt = 0;

    float acc[4][8][4];
#pragma unroll
    for (int a = 0; a < 4; a++)
#pragma unroll
        for (int b = 0; b < 8; b++)
#pragma unroll
            for (int c = 0; c < 4; c++) acc[a][b][c] = 0.f;

    // loader: per stage, per matrix 128 rows x 4x16B chunks = 512; 4 passes of 128 thr
    auto load_stage = [&](int ks, int buf) {
        uint32_t sa = sbase + buf * STAGE_BYTES;
        uint32_t sb = sa + 128 * 80;
#pragma unroll
        for (int i = 0; i < 4; i++) {
            int ch = tid + i * 128;      // 0..511
            int r = ch >> 2;             // row 0..127
            int c = ch & 3;              // 16B chunk
            const __half* srcA = Ag + (size_t)r * D_DIM + ks * KC + c * 8;
            const __half* srcB = Bg + (size_t)r * D_DIM + ks * KC + c * 8;
            asm volatile("cp.async.cg.shared.global [%0], [%1], 16;"
                         :: "r"(sa + r * 80 + c * 16), "l"(srcA));
            asm volatile("cp.async.cg.shared.global [%0], [%1], 16;"
                         :: "r"(sb + r * 80 + c * 16), "l"(srcB));
        }
    };

#pragma unroll
    for (int p = 0; p < NSTG - 1; p++) {
        load_stage(p, p);
        asm volatile("cp.async.commit_group;");
    }

#pragma unroll 1
    for (int s = 0; s < KSTAGES; s++) {
        if (s < KSTAGES - 1) asm volatile("cp.async.wait_group 1;");
        else                 asm volatile("cp.async.wait_group 0;");
        __syncthreads();

        int nxt = s + NSTG - 1;
        if (nxt < KSTAGES) load_stage(nxt, nxt % NSTG);
        asm volatile("cp.async.commit_group;");

        uint32_t sa = sbase + (s % NSTG) * STAGE_BYTES;
        uint32_t sb = sa + 128 * 80;
#pragma unroll
        for (int kk = 0; kk < 2; kk++) {
            int k0 = kk * 16;
            uint32_t a[4][4], b[8][2];
#pragma unroll
            for (int mi = 0; mi < 4; mi++) {
                int row = wm * 64 + mi * 16 + (lane & 15);
                int col = k0 + ((lane >> 4) << 3);
                uint32_t addr = sa + row * 80 + col * 2;
                asm volatile("ldmatrix.sync.aligned.m8n8.x4.shared.b16 {%0,%1,%2,%3}, [%4];"
                             : "=r"(a[mi][0]), "=r"(a[mi][1]), "=r"(a[mi][2]), "=r"(a[mi][3])
                             : "r"(addr));
            }
#pragma unroll
            for (int p = 0; p < 4; p++) {    // one x4 = 16 n-rows x k16
                int g = lane >> 3;
                int rr = lane & 7;
                int row = wn * 64 + p * 16 + ((g & 2) ? 8 : 0) + rr;
                int col = k0 + ((g & 1) ? 8 : 0);
                uint32_t addr = sb + row * 80 + col * 2;
                asm volatile("ldmatrix.sync.aligned.m8n8.x4.shared.b16 {%0,%1,%2,%3}, [%4];"
                             : "=r"(b[2 * p][0]), "=r"(b[2 * p][1]),
                               "=r"(b[2 * p + 1][0]), "=r"(b[2 * p + 1][1])
                             : "r"(addr));
            }
#pragma unroll
            for (int mi = 0; mi < 4; mi++)
#pragma unroll
                for (int ni = 0; ni < 8; ni++)
                    asm volatile(
                        "mma.sync.aligned.m16n8k16.row.col.f32.f16.f16.f32 "
                        "{%0,%1,%2,%3}, {%4,%5,%6,%7}, {%8,%9}, {%0,%1,%2,%3};"
                        : "+f"(acc[mi][ni][0]), "+f"(acc[mi][ni][1]),
                          "+f"(acc[mi][ni][2]), "+f"(acc[mi][ni][3])
                        : "r"(a[mi][0]), "r"(a[mi][1]), "r"(a[mi][2]), "r"(a[mi][3]),
                          "r"(b[ni][0]), "r"(b[ni][1]));
        }
    }

    // label collection for the fused margin (visibility covered by syncs below)
    {
        int l = labels[m0 + tid];
        if (l >= n0 && l < n0 + 128) {
            int idx = atomicAdd(&s_cnt, 1);
            s_rows[idx] = tid;
        }
    }

    // ------- epilogue: two 64-row halves through smem, coalesced stores -----
    float* sT = (float*)smem;              // 64 x EPI_LDC fp32 (33.8 KB <= 60 KB)
    int c4 = lane * 4;
    int cg = n0 + c4;
    bool okc = (cg < C_TOT);

#pragma unroll 1
    for (int half = 0; half < 2; half++) {
        __syncthreads();                   // half 0: mainloop smem done; half 1: stores done
        if (wm == half) {
#pragma unroll
            for (int mi = 0; mi < 4; mi++) {
                int r0 = mi * 16 + (lane >> 2);
#pragma unroll
                for (int ni = 0; ni < 8; ni++) {
                    int c0 = wn * 64 + ni * 8 + (lane & 3) * 2;
                    float2 v0, v1;
                    v0.x = SSCALE * fminf(1.f, fmaxf(-1.f, acc[mi][ni][0]));
                    v0.y = SSCALE * fminf(1.f, fmaxf(-1.f, acc[mi][ni][1]));
                    v1.x = SSCALE * fminf(1.f, fmaxf(-1.f, acc[mi][ni][2]));
                    v1.y = SSCALE * fminf(1.f, fmaxf(-1.f, acc[mi][ni][3]));
                    *(float2*)&sT[r0 * EPI_LDC + c0] = v0;
                    *(float2*)&sT[(r0 + 8) * EPI_LDC + c0] = v1;
                }
            }
        }
        __syncthreads();
        if (okc) {
#pragma unroll
            for (int it = 0; it < 16; it++) {
                int r = it * 4 + warp;
                float4 v = *(float4*)&sT[r * EPI_LDC + c4];
                *(float4*)&out[(size_t)(m0 + half * 64 + r) * C_TOT + cg] = v;
            }
        }
    }
    __syncthreads();   // order plain stores before margin overwrite

    // ------- fused exact-fp32 margin fixup (expected ~0.16 rows per CTA) -----
    int cnt = s_cnt;
    for (int e = warp; e < cnt; e += 4) {
        int r = s_rows[e];
        int lbl = labels[m0 + r];
        const float* fr = f + (size_t)(m0 + r) * D_DIM;
        const float* wr = w + (size_t)lbl * D_DIM;
        float ff = 0.f, ww = 0.f, fw = 0.f;
#pragma unroll
        for (int i = lane; i < D_DIM; i += 32) {
            float av = fr[i], bv = wr[i];
            ff += av * av; ww += bv * bv; fw += av * bv;
        }
#pragma unroll
        for (int o = 16; o; o >>= 1) {
            ff += __shfl_xor_sync(0xffffffffu, ff, o);
            ww += __shfl_xor_sync(0xffffffffu, ww, o);
            fw += __shfl_xor_sync(0xffffffffu, fw, o);
        }
        if (lane == 0) {
            float cosv = fw * rsqrtf(ff + 1e-12f) * rsqrtf(ww + 1e-12f);
            cosv = fminf(1.f, fmaxf(-1.f, cosv));
            const float TH = -0.8775825618903728f;   // cos(pi - 0.5)
            const float MM = 0.2397127693021015f;    // sin(pi - 0.5) * 0.5
            float adj = (cosv > TH) ? cosf(acosf(cosv) + 0.5f) : (cosv - MM);
            out[(size_t)(m0 + r) * C_TOT + lbl] = SSCALE * adj;
        }
    }
}

// ---------------------------------------------------------------------------
// Launch: best-measured schedule (uniform 98-tile chunks, 8 chunks) with the
// warp-per-row feature normalization.
// ---------------------------------------------------------------------------
extern "C" void kernel_launch(void* const* d_in, const int* in_sizes, int n_in,
                              void* d_out, int out_size) {
    const float* features = (const float*)d_in[0];   // [512, 512] f32
    const int*   labels   = (const int*)d_in[1];     // [512] i32
    const float* weight   = (const float*)d_in[2];   // [100000, 512] f32
    float* out = (float*)d_out;                      // [512, 100000] f32

    static const int ntc[NCHUNK] = {98, 98, 98, 98, 98, 98, 97, 97}; // sum 782
    static cudaStream_t s1 = nullptr, s2 = nullptr;
    static cudaEvent_t e_root, e_nf, e_w[NCHUNK], e_g2;
    if (s1 == nullptr) {
        cudaStreamCreateWithFlags(&s1, cudaStreamNonBlocking);
        cudaStreamCreateWithFlags(&s2, cudaStreamNonBlocking);
        cudaEventCreateWithFlags(&e_root, cudaEventDisableTiming);
        cudaEventCreateWithFlags(&e_nf, cudaEventDisableTiming);
        cudaEventCreateWithFlags(&e_g2, cudaEventDisableTiming);
        for (int c = 0; c < NCHUNK; c++)
            cudaEventCreateWithFlags(&e_w[c], cudaEventDisableTiming);
        cudaFuncSetAttribute(k_gemm, cudaFuncAttributeMaxDynamicSharedMemorySize, GEMM_SMEM);
    }

    // fork point: s1/s2 join the (possibly capturing) default stream's graph
    cudaEventRecord(e_root, 0);
    cudaStreamWaitEvent(s1, e_root, 0);
    cudaStreamWaitEvent(s2, e_root, 0);

    // features on s0 (fast warp-per-row version)
    k_norm_features<<<B_DIM / 8, 256>>>(features);
    cudaEventRecord(e_nf, 0);
    cudaStreamWaitEvent(s2, e_nf, 0);    // s2 gemms also need nf

    // W-normalization chunks on s1
    int row_base = 0;
    for (int c = 0; c < NCHUNK; c++) {
        int nrows = ntc[c] * 128;
        k_norm_weights<<<nrows / 8, 256, 0, s1>>>(weight, row_base, nrows);
        cudaEventRecord(e_w[c], s1);
        row_base += nrows;
    }

    // GEMM chunks: even on s0, odd on s2
    int nt_off = 0;
    for (int c = 0; c < NCHUNK; c++) {
        cudaStream_t gs = (c & 1) ? s2 : (cudaStream_t)0;
        cudaStreamWaitEvent(gs, e_w[c], 0);
        k_gemm<<<4 * ntc[c], 128, GEMM_SMEM, gs>>>(features, labels, weight, out, nt_off);
        nt_off += ntc[c];
    }

    // join s2 back into s0
    cudaEventRecord(e_g2, s2);
    cudaStreamWaitEvent(0, e_g2, 0);
}